// round 1
// baseline (speedup 1.0000x reference)
#include <cuda_runtime.h>

#define TOK 16384
#define LSEQ 4096
#define NB 4
#define DMO 64      // input/output dim D
#define DM 128      // d_model of mamba (2D)
#define DI 256      // d_inner
#define DS 16       // d_state
#define DTR 8       // dt_rank

// ---------------- scratch (device globals; no runtime allocation) ----------------
__device__ float g_Wu[DM * DMO];    // combined W_fp @ W_ip
__device__ float g_bu[DM];
__device__ float g_xn[TOK * DMO];   // rmsnorm1(x)
__device__ float g_u[TOK * DM];     // mamba input u
__device__ float g_xraw[TOK * DI];  // pre-conv x branch
__device__ float g_xc[TOK * DI];    // post-conv silu x
__device__ float g_zs[TOK * DI];    // silu(z)
__device__ float g_delta[TOK * DI];
__device__ float g_Bm[TOK * DS];
__device__ float g_Cm[TOK * DS];
__device__ float g_y[NB * DI * LSEQ]; // gated scan output, layout (b, d, L)
__device__ float g_m[TOK * DM];     // rmsnorm2(mamba_out) + u

// ---------------- K0: compose W_u = W_fp @ W_ip, b_u = W_fp@b_ip + b_fp ----------
__global__ void k_combine(const float* __restrict__ Wfp, const float* __restrict__ Wip,
                          const float* __restrict__ bip, const float* __restrict__ bfp) {
    int tid = threadIdx.x;
    for (int idx = tid; idx < DM * DMO; idx += blockDim.x) {
        int o = idx / DMO, i = idx % DMO;
        float s = 0.f;
        for (int k = 0; k < DM; ++k) s = fmaf(Wfp[o * DM + k], Wip[k * DMO + i], s);
        g_Wu[idx] = s;
    }
    if (tid < DM) {
        float s = bfp[tid];
        for (int k = 0; k < DM; ++k) s = fmaf(Wfp[tid * DM + k], bip[k], s);
        g_bu[tid] = s;
    }
}

// ---------------- K1: rmsnorm1 + u = W_u @ xn + b_u (64 tokens / block) ----------
__global__ void k_rms_u(const float* __restrict__ x, const float* __restrict__ wn1) {
    extern __shared__ float sm[];
    float* sx  = sm;                 // 64*64 normalized x
    float* swT = sm + 64 * DMO;      // [i][o] padded 129
    float* ssc = swT + DMO * 129;    // 64 scales
    int tid = threadIdx.x;
    long t0 = (long)blockIdx.x * 64;

    for (int idx = tid; idx < 64 * DMO; idx += 256) sx[idx] = x[t0 * DMO + idx];
    __syncthreads();
    if (tid < 64) {
        float ss = 0.f;
        for (int i = 0; i < DMO; ++i) { float v = sx[tid * DMO + i]; ss = fmaf(v, v, ss); }
        ssc[tid] = rsqrtf(ss * (1.f / DMO) + 1e-5f);
    }
    __syncthreads();
    for (int idx = tid; idx < 64 * DMO; idx += 256) {
        int t = idx / DMO, i = idx % DMO;
        float v = sx[idx] * ssc[t] * wn1[i];
        sx[idx] = v;
        g_xn[t0 * DMO + idx] = v;
    }
    for (int idx = tid; idx < DM * DMO; idx += 256) {
        int o = idx / DMO, i = idx % DMO;
        swT[i * 129 + o] = g_Wu[idx];
    }
    __syncthreads();
    int tx = tid & 31, ty = tid >> 5;
    float acc[8][4] = {};
    for (int i = 0; i < DMO; ++i) {
        float wv[4];
        #pragma unroll
        for (int j = 0; j < 4; ++j) wv[j] = swT[i * 129 + tx + 32 * j];
        #pragma unroll
        for (int r = 0; r < 8; ++r) {
            float xv = sx[(ty * 8 + r) * DMO + i];
            #pragma unroll
            for (int j = 0; j < 4; ++j) acc[r][j] = fmaf(xv, wv[j], acc[r][j]);
        }
    }
    for (int r = 0; r < 8; ++r)
        for (int j = 0; j < 4; ++j) {
            int t = ty * 8 + r, o = tx + 32 * j;
            g_u[(t0 + t) * DM + o] = acc[r][j] + g_bu[o];
        }
}

// ---------------- K2: xz = in_proj @ u ; split into x_raw and silu(z) ------------
__global__ void k_inproj(const float* __restrict__ Win) {
    extern __shared__ float sm[];
    float* su  = sm;              // 64*128 [t][i]
    float* swT = sm + 64 * DM;    // [i][e] padded 129
    int tid = threadIdx.x;
    long t0 = (long)blockIdx.x * 64;
    int e0 = blockIdx.y * 128;

    for (int idx = tid; idx < 64 * DM; idx += 256) su[idx] = g_u[t0 * DM + idx];
    for (int idx = tid; idx < 128 * DM; idx += 256) {
        int e = idx >> 7, i = idx & 127;
        swT[i * 129 + e] = Win[(long)(e0 + e) * DM + i];
    }
    __syncthreads();
    int tx = tid & 31, ty = tid >> 5;
    float acc[8][4] = {};
    for (int i = 0; i < DM; ++i) {
        float wv[4];
        #pragma unroll
        for (int j = 0; j < 4; ++j) wv[j] = swT[i * 129 + tx + 32 * j];
        #pragma unroll
        for (int r = 0; r < 8; ++r) {
            float xv = su[(ty * 8 + r) * DM + i];
            #pragma unroll
            for (int j = 0; j < 4; ++j) acc[r][j] = fmaf(xv, wv[j], acc[r][j]);
        }
    }
    for (int r = 0; r < 8; ++r)
        for (int j = 0; j < 4; ++j) {
            long tg = t0 + ty * 8 + r;
            int eg = e0 + tx + 32 * j;
            float v = acc[r][j];
            if (eg < DI) g_xraw[tg * DI + eg] = v;
            else         g_zs[tg * DI + (eg - DI)] = v / (1.f + __expf(-v));
        }
}

// ---------------- K3: causal depthwise conv (k=4) + bias + silu ------------------
__global__ void k_conv(const float* __restrict__ cw, const float* __restrict__ cb) {
    int t = blockIdx.x;
    int d = threadIdx.x;
    int l = t & (LSEQ - 1);
    float acc = cb[d];
    #pragma unroll
    for (int j = 0; j < 4; ++j) {
        int lj = l - 3 + j;
        if (lj >= 0) acc = fmaf(cw[d * 4 + j], g_xraw[(long)(t - 3 + j) * DI + d], acc);
    }
    acc = acc / (1.f + __expf(-acc));
    g_xc[(long)t * DI + d] = acc;
}

// ---------------- K4: x_dbl = x_proj @ x ; B,C split ; delta = softplus(...) -----
__global__ void k_xproj(const float* __restrict__ Xp, const float* __restrict__ Wdt,
                        const float* __restrict__ bdt) {
    extern __shared__ float sm[];
    float* sx   = sm;                    // 64*257 (padded)
    float* spT  = sm + 64 * 257;         // [k][e] padded 41
    float* sdbl = spT + 256 * 41;        // 64*40
    int tid = threadIdx.x;
    long t0 = (long)blockIdx.x * 64;

    for (int idx = tid; idx < 64 * DI; idx += 256) {
        int t = idx >> 8, k = idx & 255;
        sx[t * 257 + k] = g_xc[t0 * DI + idx];
    }
    for (int idx = tid; idx < 40 * DI; idx += 256) {
        int e = idx >> 8, k = idx & 255;
        spT[k * 41 + e] = Xp[idx];
    }
    __syncthreads();
    {
        int t = tid >> 2, eb = (tid & 3) * 10;
        float acc[10] = {};
        for (int k = 0; k < DI; ++k) {
            float xv = sx[t * 257 + k];
            #pragma unroll
            for (int e = 0; e < 10; ++e) acc[e] = fmaf(xv, spT[k * 41 + eb + e], acc[e]);
        }
        for (int e = 0; e < 10; ++e) sdbl[t * 40 + eb + e] = acc[e];
    }
    __syncthreads();
    for (int idx = tid; idx < 64 * DS; idx += 256) {
        int t = idx >> 4, s = idx & 15;
        g_Bm[(t0 + t) * DS + s] = sdbl[t * 40 + 8 + s];
        g_Cm[(t0 + t) * DS + s] = sdbl[t * 40 + 24 + s];
    }
    int d = tid;
    float wr[8];
    #pragma unroll
    for (int r = 0; r < 8; ++r) wr[r] = Wdt[d * 8 + r];
    float bb = bdt[d];
    for (int t = 0; t < 64; ++t) {
        float pre = bb;
        #pragma unroll
        for (int r = 0; r < 8; ++r) pre = fmaf(sdbl[t * 40 + r], wr[r], pre);
        float sp = (pre > 20.f) ? pre : log1pf(__expf(pre));
        g_delta[(t0 + t) * DI + d] = sp;
    }
}

// ---------------- K5: selective scan (16 lanes = 16 states per channel) ----------
// y[b,d,L] = ((sum_s h*C) + x*D) * silu(z), fused gating in epilogue.
__global__ void k_scan(const float* __restrict__ Alog, const float* __restrict__ Dp_) {
    int c = threadIdx.x >> 4;
    int s = threadIdx.x & 15;
    int ch = blockIdx.x * 8 + c;        // 1024 channels total
    int b = ch >> 8;
    int d = ch & 255;
    float Aval = -expf(Alog[d * DS + s]);
    float Dp = Dp_[d];
    const float* pd = g_delta + (long)b * LSEQ * DI + d;
    const float* px = g_xc    + (long)b * LSEQ * DI + d;
    const float* pz = g_zs    + (long)b * LSEQ * DI + d;
    const float* pB = g_Bm    + (long)b * LSEQ * DS + s;
    const float* pC = g_Cm    + (long)b * LSEQ * DS + s;
    float* py = g_y + ((long)b * DI + d) * LSEQ;
    float h = 0.f;
    #pragma unroll 4
    for (int t = 0; t < LSEQ; ++t) {
        float dv = pd[(long)t * DI];
        float xv = px[(long)t * DI];
        float Bv = pB[(long)t * DS];
        float Cv = pC[(long)t * DS];
        float a = __expf(dv * Aval);
        h = fmaf(a, h, dv * xv * Bv);
        float p = h * Cv;
        p += __shfl_xor_sync(0xffffffffu, p, 8);
        p += __shfl_xor_sync(0xffffffffu, p, 4);
        p += __shfl_xor_sync(0xffffffffu, p, 2);
        p += __shfl_xor_sync(0xffffffffu, p, 1);
        if (s == 0) py[t] = (p + xv * Dp) * pz[(long)t * DI];
    }
}

// ---------------- K6: m = rmsnorm2(mamba_out @ y) + u -----------------------------
__global__ void k_outproj(const float* __restrict__ Wmo, const float* __restrict__ wn2) {
    extern __shared__ float sm[];
    float* syT = sm;               // [k][tl] 256*64
    float* swT = sm + DI * 64;     // [k][o] padded 129
    int tid = threadIdx.x;
    long t0 = (long)blockIdx.x * 64;
    int b = (int)(t0 >> 12);
    int lpos = (int)(t0 & (LSEQ - 1));

    for (int idx = tid; idx < DI * 64; idx += 256) {
        int k = idx >> 6, tl = idx & 63;
        syT[idx] = g_y[((long)b * DI + k) * LSEQ + lpos + tl];
    }
    for (int idx = tid; idx < DM * DI; idx += 256) {
        int o = idx >> 8, k = idx & 255;
        swT[k * 129 + o] = Wmo[idx];
    }
    __syncthreads();
    int tx = tid & 31, ty = tid >> 5;
    float acc[8][4] = {};
    for (int k = 0; k < DI; ++k) {
        float wv[4];
        #pragma unroll
        for (int j = 0; j < 4; ++j) wv[j] = swT[k * 129 + tx + 32 * j];
        #pragma unroll
        for (int r = 0; r < 8; ++r) {
            float yv = syT[k * 64 + ty * 8 + r];
            #pragma unroll
            for (int j = 0; j < 4; ++j) acc[r][j] = fmaf(yv, wv[j], acc[r][j]);
        }
    }
    // rmsnorm over the 128 outputs of each token (spread across 32 lanes, 4 each)
    for (int r = 0; r < 8; ++r) {
        float ss = 0.f;
        #pragma unroll
        for (int j = 0; j < 4; ++j) ss = fmaf(acc[r][j], acc[r][j], ss);
        #pragma unroll
        for (int off = 16; off >= 1; off >>= 1) ss += __shfl_xor_sync(0xffffffffu, ss, off);
        float sc = rsqrtf(ss * (1.f / DM) + 1e-5f);
        long t = t0 + ty * 8 + r;
        #pragma unroll
        for (int j = 0; j < 4; ++j) {
            int o = tx + 32 * j;
            g_m[t * DM + o] = acc[r][j] * sc * wn2[o] + g_u[t * DM + o];
        }
    }
}

// ---------------- K7: w = swish(W_wp@xn+b) ; out = W_op@(w*m)+b + x ---------------
__global__ void k_final(const float* __restrict__ Wwp, const float* __restrict__ bwp,
                        const float* __restrict__ Wop, const float* __restrict__ bop,
                        const float* __restrict__ x, float* __restrict__ out) {
    extern __shared__ float sm[];
    float* smm  = sm;                      // 64*130 (m, then p = w*m)
    float* sxn  = smm + 64 * 130;          // 64*64
    float* swpT = sxn + 64 * DMO;          // [i][c] padded 129
    float* sopT = swpT + DMO * 129;        // [c][o] padded 65
    int tid = threadIdx.x;
    long t0 = (long)blockIdx.x * 64;

    for (int idx = tid; idx < 64 * DM; idx += 256) {
        int t = idx >> 7, c = idx & 127;
        smm[t * 130 + c] = g_m[t0 * DM + idx];
    }
    for (int idx = tid; idx < 64 * DMO; idx += 256) sxn[idx] = g_xn[t0 * DMO + idx];
    for (int idx = tid; idx < DM * DMO; idx += 256) {
        int c = idx >> 6, i = idx & 63;
        swpT[i * 129 + c] = Wwp[idx];
    }
    for (int idx = tid; idx < DMO * DM; idx += 256) {
        int o = idx >> 7, c = idx & 127;
        sopT[c * 65 + o] = Wop[idx];
    }
    __syncthreads();
    int tx = tid & 31, ty = tid >> 5;
    {
        float acc[8][4] = {};
        for (int i = 0; i < DMO; ++i) {
            float wv[4];
            #pragma unroll
            for (int j = 0; j < 4; ++j) wv[j] = swpT[i * 129 + tx + 32 * j];
            #pragma unroll
            for (int r = 0; r < 8; ++r) {
                float xv = sxn[(ty * 8 + r) * DMO + i];
                #pragma unroll
                for (int j = 0; j < 4; ++j) acc[r][j] = fmaf(xv, wv[j], acc[r][j]);
            }
        }
        for (int r = 0; r < 8; ++r)
            for (int j = 0; j < 4; ++j) {
                int c = tx + 32 * j;
                float v = acc[r][j] + bwp[c];
                float w = v / (1.f + __expf(-v));
                smm[(ty * 8 + r) * 130 + c] *= w;
            }
    }
    __syncthreads();
    {
        int t = tid >> 2;
        int ob = (tid & 3) * 16;
        float acc[16] = {};
        for (int c = 0; c < DM; ++c) {
            float pv = smm[t * 130 + c];
            #pragma unroll
            for (int j = 0; j < 16; ++j) acc[j] = fmaf(pv, sopT[c * 65 + ob + j], acc[j]);
        }
        long tg = t0 + t;
        #pragma unroll
        for (int j = 0; j < 16; ++j) {
            int o = ob + j;
            out[tg * DMO + o] = acc[j] + bop[o] + x[tg * DMO + o];
        }
    }
}

// ---------------- launch -----------------------------------------------------------
extern "C" void kernel_launch(void* const* d_in, const int* in_sizes, int n_in,
                              void* d_out, int out_size) {
    const float* x    = (const float*)d_in[0];
    const float* wn1  = (const float*)d_in[1];
    const float* wn2  = (const float*)d_in[2];
    const float* Wip  = (const float*)d_in[3];
    const float* bip  = (const float*)d_in[4];
    const float* Wfp  = (const float*)d_in[5];
    const float* bfp  = (const float*)d_in[6];
    const float* Wwp  = (const float*)d_in[7];
    const float* bwp  = (const float*)d_in[8];
    const float* Wop  = (const float*)d_in[9];
    const float* bop  = (const float*)d_in[10];
    const float* Win  = (const float*)d_in[11];
    const float* cw   = (const float*)d_in[12];
    const float* cb   = (const float*)d_in[13];
    const float* Xp   = (const float*)d_in[14];
    const float* Wdt  = (const float*)d_in[15];
    const float* bdt  = (const float*)d_in[16];
    const float* Alog = (const float*)d_in[17];
    const float* Dpar = (const float*)d_in[18];
    const float* Wmo  = (const float*)d_in[19];
    float* out = (float*)d_out;

    const int SM_K1 = (64 * 64 + 64 * 129 + 64) * 4;
    const int SM_K2 = (64 * 128 + 128 * 129) * 4;
    const int SM_K4 = (64 * 257 + 256 * 41 + 64 * 40) * 4;
    const int SM_K6 = (256 * 64 + 256 * 129) * 4;
    const int SM_K7 = (64 * 130 + 64 * 64 + 64 * 129 + 128 * 65) * 4;

    cudaFuncSetAttribute(k_rms_u,   cudaFuncAttributeMaxDynamicSharedMemorySize, SM_K1);
    cudaFuncSetAttribute(k_inproj,  cudaFuncAttributeMaxDynamicSharedMemorySize, SM_K2);
    cudaFuncSetAttribute(k_xproj,   cudaFuncAttributeMaxDynamicSharedMemorySize, SM_K4);
    cudaFuncSetAttribute(k_outproj, cudaFuncAttributeMaxDynamicSharedMemorySize, SM_K6);
    cudaFuncSetAttribute(k_final,   cudaFuncAttributeMaxDynamicSharedMemorySize, SM_K7);

    k_combine<<<1, 256>>>(Wfp, Wip, bip, bfp);
    k_rms_u<<<TOK / 64, 256, SM_K1>>>(x, wn1);
    k_inproj<<<dim3(TOK / 64, 4), 256, SM_K2>>>(Win);
    k_conv<<<TOK, DI>>>(cw, cb);
    k_xproj<<<TOK / 64, 256, SM_K4>>>(Xp, Wdt, bdt);
    k_scan<<<128, 128>>>(Alog, Dpar);
    k_outproj<<<TOK / 64, 256, SM_K6>>>(Wmo, wn2);
    k_final<<<TOK / 64, 256, SM_K7>>>(Wwp, bwp, Wop, bop, x, out);
}

// round 2
// speedup vs baseline: 3.9648x; 3.9648x over previous
#include <cuda_runtime.h>

#define TOK 16384
#define LSEQ 4096
#define NB 4
#define DMO 64      // input/output dim D
#define DM 128      // d_model of mamba (2D)
#define DI 256      // d_inner
#define DS 16       // d_state
#define DTR 8       // dt_rank
#define NCH 1024    // NB * DI channels
#define CHK 64      // chunk length
#define NG (LSEQ / CHK)   // 64 chunks
#define NUNIT (NCH * NG)  // 65536 units

// ---------------- scratch (device globals; no runtime allocation) ----------------
__device__ float g_Wu[DM * DMO];    // combined W_fp @ W_ip
__device__ float g_bu[DM];
__device__ float g_xn[TOK * DMO];   // rmsnorm1(x)
__device__ float g_u[TOK * DM];     // mamba input u
__device__ float g_xraw[TOK * DI];  // pre-conv x branch
__device__ float g_xc[TOK * DI];    // post-conv silu x
__device__ float g_zs[TOK * DI];    // silu(z)
__device__ float g_delta[TOK * DI];
__device__ float g_Bm[TOK * DS];
__device__ float g_Cm[TOK * DS];
__device__ float g_y[NB * DI * LSEQ]; // gated scan output, layout (b, d, L)
__device__ float g_m[TOK * DM];     // rmsnorm2(mamba_out) + u
__device__ float g_P[NUNIT * DS];   // per-chunk state decay product
__device__ float g_q[NUNIT * DS];   // per-chunk local final state (h_in = 0)
__device__ float g_hin[NUNIT * DS]; // per-chunk incoming state

// ---------------- K0: compose W_u = W_fp @ W_ip, b_u = W_fp@b_ip + b_fp ----------
__global__ void k_combine(const float* __restrict__ Wfp, const float* __restrict__ Wip,
                          const float* __restrict__ bip, const float* __restrict__ bfp) {
    int tid = threadIdx.x;
    for (int idx = tid; idx < DM * DMO; idx += blockDim.x) {
        int o = idx / DMO, i = idx % DMO;
        float s = 0.f;
        for (int k = 0; k < DM; ++k) s = fmaf(Wfp[o * DM + k], Wip[k * DMO + i], s);
        g_Wu[idx] = s;
    }
    if (tid < DM) {
        float s = bfp[tid];
        for (int k = 0; k < DM; ++k) s = fmaf(Wfp[tid * DM + k], bip[k], s);
        g_bu[tid] = s;
    }
}

// ---------------- K1: rmsnorm1 + u = W_u @ xn + b_u (64 tokens / block) ----------
__global__ void k_rms_u(const float* __restrict__ x, const float* __restrict__ wn1) {
    extern __shared__ float sm[];
    float* sx  = sm;                 // 64*64 normalized x
    float* swT = sm + 64 * DMO;      // [i][o] padded 129
    float* ssc = swT + DMO * 129;    // 64 scales
    int tid = threadIdx.x;
    long t0 = (long)blockIdx.x * 64;

    for (int idx = tid; idx < 64 * DMO; idx += 256) sx[idx] = x[t0 * DMO + idx];
    __syncthreads();
    if (tid < 64) {
        float ss = 0.f;
        for (int i = 0; i < DMO; ++i) { float v = sx[tid * DMO + i]; ss = fmaf(v, v, ss); }
        ssc[tid] = rsqrtf(ss * (1.f / DMO) + 1e-5f);
    }
    __syncthreads();
    for (int idx = tid; idx < 64 * DMO; idx += 256) {
        int t = idx / DMO, i = idx % DMO;
        float v = sx[idx] * ssc[t] * wn1[i];
        sx[idx] = v;
        g_xn[t0 * DMO + idx] = v;
    }
    for (int idx = tid; idx < DM * DMO; idx += 256) {
        int o = idx / DMO, i = idx % DMO;
        swT[i * 129 + o] = g_Wu[idx];
    }
    __syncthreads();
    int tx = tid & 31, ty = tid >> 5;
    float acc[8][4] = {};
    for (int i = 0; i < DMO; ++i) {
        float wv[4];
        #pragma unroll
        for (int j = 0; j < 4; ++j) wv[j] = swT[i * 129 + tx + 32 * j];
        #pragma unroll
        for (int r = 0; r < 8; ++r) {
            float xv = sx[(ty * 8 + r) * DMO + i];
            #pragma unroll
            for (int j = 0; j < 4; ++j) acc[r][j] = fmaf(xv, wv[j], acc[r][j]);
        }
    }
    for (int r = 0; r < 8; ++r)
        for (int j = 0; j < 4; ++j) {
            int t = ty * 8 + r, o = tx + 32 * j;
            g_u[(t0 + t) * DM + o] = acc[r][j] + g_bu[o];
        }
}

// ---------------- K2: xz = in_proj @ u ; split into x_raw and silu(z) ------------
__global__ void k_inproj(const float* __restrict__ Win) {
    extern __shared__ float sm[];
    float* su  = sm;              // 64*128 [t][i]
    float* swT = sm + 64 * DM;    // [i][e] padded 129
    int tid = threadIdx.x;
    long t0 = (long)blockIdx.x * 64;
    int e0 = blockIdx.y * 128;

    for (int idx = tid; idx < 64 * DM; idx += 256) su[idx] = g_u[t0 * DM + idx];
    for (int idx = tid; idx < 128 * DM; idx += 256) {
        int e = idx >> 7, i = idx & 127;
        swT[i * 129 + e] = Win[(long)(e0 + e) * DM + i];
    }
    __syncthreads();
    int tx = tid & 31, ty = tid >> 5;
    float acc[8][4] = {};
    for (int i = 0; i < DM; ++i) {
        float wv[4];
        #pragma unroll
        for (int j = 0; j < 4; ++j) wv[j] = swT[i * 129 + tx + 32 * j];
        #pragma unroll
        for (int r = 0; r < 8; ++r) {
            float xv = su[(ty * 8 + r) * DM + i];
            #pragma unroll
            for (int j = 0; j < 4; ++j) acc[r][j] = fmaf(xv, wv[j], acc[r][j]);
        }
    }
    for (int r = 0; r < 8; ++r)
        for (int j = 0; j < 4; ++j) {
            long tg = t0 + ty * 8 + r;
            int eg = e0 + tx + 32 * j;
            float v = acc[r][j];
            if (eg < DI) g_xraw[tg * DI + eg] = v;
            else         g_zs[tg * DI + (eg - DI)] = v / (1.f + __expf(-v));
        }
}

// ---------------- K3: causal depthwise conv (k=4) + bias + silu ------------------
__global__ void k_conv(const float* __restrict__ cw, const float* __restrict__ cb) {
    int t = blockIdx.x;
    int d = threadIdx.x;
    int l = t & (LSEQ - 1);
    float acc = cb[d];
    #pragma unroll
    for (int j = 0; j < 4; ++j) {
        int lj = l - 3 + j;
        if (lj >= 0) acc = fmaf(cw[d * 4 + j], g_xraw[(long)(t - 3 + j) * DI + d], acc);
    }
    acc = acc / (1.f + __expf(-acc));
    g_xc[(long)t * DI + d] = acc;
}

// ---------------- K4: x_dbl = x_proj @ x ; B,C split ; delta = softplus(...) -----
__global__ void k_xproj(const float* __restrict__ Xp, const float* __restrict__ Wdt,
                        const float* __restrict__ bdt) {
    extern __shared__ float sm[];
    float* sx   = sm;                    // 64*257 (padded)
    float* spT  = sm + 64 * 257;         // [k][e] padded 41
    float* sdbl = spT + 256 * 41;        // 64*40
    int tid = threadIdx.x;
    long t0 = (long)blockIdx.x * 64;

    for (int idx = tid; idx < 64 * DI; idx += 256) {
        int t = idx >> 8, k = idx & 255;
        sx[t * 257 + k] = g_xc[t0 * DI + idx];
    }
    for (int idx = tid; idx < 40 * DI; idx += 256) {
        int e = idx >> 8, k = idx & 255;
        spT[k * 41 + e] = Xp[idx];
    }
    __syncthreads();
    {
        int t = tid >> 2, eb = (tid & 3) * 10;
        float acc[10] = {};
        for (int k = 0; k < DI; ++k) {
            float xv = sx[t * 257 + k];
            #pragma unroll
            for (int e = 0; e < 10; ++e) acc[e] = fmaf(xv, spT[k * 41 + eb + e], acc[e]);
        }
        for (int e = 0; e < 10; ++e) sdbl[t * 40 + eb + e] = acc[e];
    }
    __syncthreads();
    for (int idx = tid; idx < 64 * DS; idx += 256) {
        int t = idx >> 4, s = idx & 15;
        g_Bm[(t0 + t) * DS + s] = sdbl[t * 40 + 8 + s];
        g_Cm[(t0 + t) * DS + s] = sdbl[t * 40 + 24 + s];
    }
    int d = tid;
    float wr[8];
    #pragma unroll
    for (int r = 0; r < 8; ++r) wr[r] = Wdt[d * 8 + r];
    float bb = bdt[d];
    for (int t = 0; t < 64; ++t) {
        float pre = bb;
        #pragma unroll
        for (int r = 0; r < 8; ++r) pre = fmaf(sdbl[t * 40 + r], wr[r], pre);
        float sp = (pre > 20.f) ? pre : log1pf(__expf(pre));
        g_delta[(t0 + t) * DI + d] = sp;
    }
}

// ---------------- K5a: per-chunk decay product P and local state q ----------------
// unit = (channel * NG + chunk); 16 lanes per unit (one per state).
__global__ void k_scan1(const float* __restrict__ Alog) {
    int u = threadIdx.x >> 4;
    int s = threadIdx.x & 15;
    int unit = blockIdx.x * 16 + u;
    int g = unit & (NG - 1);
    int ch = unit >> 6;
    int b = ch >> 8, d = ch & 255;
    float Aval = -__expf(Alog[d * DS + s]);
    long lbase = (long)b * LSEQ + g * CHK;
    const float* pd = g_delta + lbase * DI + d;
    const float* px = g_xc    + lbase * DI + d;
    const float* pB = g_Bm    + lbase * DS + s;
    float P = 1.f, q = 0.f;
    #pragma unroll 8
    for (int t = 0; t < CHK; ++t) {
        float dv = pd[(long)t * DI];
        float xv = px[(long)t * DI];
        float Bv = pB[t * DS];
        float a = __expf(dv * Aval);
        P *= a;
        q = fmaf(a, q, dv * xv * Bv);
    }
    long idx = (long)unit * DS + s;
    g_P[idx] = P;
    g_q[idx] = q;
}

// ---------------- K5b: propagate h_in across chunks (per channel-state) ----------
__global__ void k_scan2() {
    int tid = blockIdx.x * 256 + threadIdx.x;   // 0..16383 = channel*16 + state
    int ch = tid >> 4, s = tid & 15;
    float h = 0.f;
    long base = (long)ch * NG * DS + s;
    #pragma unroll 8
    for (int g = 0; g < NG; ++g) {
        long idx = base + (long)g * DS;
        g_hin[idx] = h;
        h = fmaf(g_P[idx], h, g_q[idx]);
    }
}

// ---------------- K5c: local scan from h_in, y = (C.h + x*D) * silu(z) -----------
__global__ void k_scan3(const float* __restrict__ Alog, const float* __restrict__ Dp_) {
    __shared__ float ybuf[16 * CHK];
    int u = threadIdx.x >> 4;
    int s = threadIdx.x & 15;
    int unit = blockIdx.x * 16 + u;
    int g = unit & (NG - 1);
    int ch = unit >> 6;
    int b = ch >> 8, d = ch & 255;
    float Aval = -__expf(Alog[d * DS + s]);
    float Dp = Dp_[d];
    long lbase = (long)b * LSEQ + g * CHK;
    const float* pd = g_delta + lbase * DI + d;
    const float* px = g_xc    + lbase * DI + d;
    const float* pz = g_zs    + lbase * DI + d;
    const float* pB = g_Bm    + lbase * DS + s;
    const float* pC = g_Cm    + lbase * DS + s;
    float h = g_hin[(long)unit * DS + s];
    #pragma unroll 4
    for (int t = 0; t < CHK; ++t) {
        float dv = pd[(long)t * DI];
        float xv = px[(long)t * DI];
        float Bv = pB[t * DS];
        float Cv = pC[t * DS];
        float a = __expf(dv * Aval);
        h = fmaf(a, h, dv * xv * Bv);
        float p = h * Cv;
        p += __shfl_xor_sync(0xffffffffu, p, 8);
        p += __shfl_xor_sync(0xffffffffu, p, 4);
        p += __shfl_xor_sync(0xffffffffu, p, 2);
        p += __shfl_xor_sync(0xffffffffu, p, 1);
        if (s == 0) ybuf[u * CHK + t] = (p + xv * Dp) * pz[(long)t * DI];
    }
    __syncthreads();
    // Block handles 16 consecutive chunks of ONE channel -> 1024 contiguous floats.
    float* py = g_y + (long)ch * LSEQ + (long)(blockIdx.x & 3) * 1024;
    for (int i = threadIdx.x; i < 16 * CHK; i += 256) py[i] = ybuf[i];
}

// ---------------- K6: m = rmsnorm2(mamba_out @ y) + u -----------------------------
__global__ void k_outproj(const float* __restrict__ Wmo, const float* __restrict__ wn2) {
    extern __shared__ float sm[];
    float* syT = sm;               // [k][tl] 256*64
    float* swT = sm + DI * 64;     // [k][o] padded 129
    int tid = threadIdx.x;
    long t0 = (long)blockIdx.x * 64;
    int b = (int)(t0 >> 12);
    int lpos = (int)(t0 & (LSEQ - 1));

    for (int idx = tid; idx < DI * 64; idx += 256) {
        int k = idx >> 6, tl = idx & 63;
        syT[idx] = g_y[((long)b * DI + k) * LSEQ + lpos + tl];
    }
    for (int idx = tid; idx < DM * DI; idx += 256) {
        int o = idx >> 8, k = idx & 255;
        swT[k * 129 + o] = Wmo[idx];
    }
    __syncthreads();
    int tx = tid & 31, ty = tid >> 5;
    float acc[8][4] = {};
    for (int k = 0; k < DI; ++k) {
        float wv[4];
        #pragma unroll
        for (int j = 0; j < 4; ++j) wv[j] = swT[k * 129 + tx + 32 * j];
        #pragma unroll
        for (int r = 0; r < 8; ++r) {
            float yv = syT[k * 64 + ty * 8 + r];
            #pragma unroll
            for (int j = 0; j < 4; ++j) acc[r][j] = fmaf(yv, wv[j], acc[r][j]);
        }
    }
    for (int r = 0; r < 8; ++r) {
        float ss = 0.f;
        #pragma unroll
        for (int j = 0; j < 4; ++j) ss = fmaf(acc[r][j], acc[r][j], ss);
        #pragma unroll
        for (int off = 16; off >= 1; off >>= 1) ss += __shfl_xor_sync(0xffffffffu, ss, off);
        float sc = rsqrtf(ss * (1.f / DM) + 1e-5f);
        long t = t0 + ty * 8 + r;
        #pragma unroll
        for (int j = 0; j < 4; ++j) {
            int o = tx + 32 * j;
            g_m[t * DM + o] = acc[r][j] * sc * wn2[o] + g_u[t * DM + o];
        }
    }
}

// ---------------- K7: w = swish(W_wp@xn+b) ; out = W_op@(w*m)+b + x ---------------
__global__ void k_final(const float* __restrict__ Wwp, const float* __restrict__ bwp,
                        const float* __restrict__ Wop, const float* __restrict__ bop,
                        const float* __restrict__ x, float* __restrict__ out) {
    extern __shared__ float sm[];
    float* smm  = sm;                      // 64*130 (m, then p = w*m)
    float* sxn  = smm + 64 * 130;          // 64*64
    float* swpT = sxn + 64 * DMO;          // [i][c] padded 129
    float* sopT = swpT + DMO * 129;        // [c][o] padded 65
    int tid = threadIdx.x;
    long t0 = (long)blockIdx.x * 64;

    for (int idx = tid; idx < 64 * DM; idx += 256) {
        int t = idx >> 7, c = idx & 127;
        smm[t * 130 + c] = g_m[t0 * DM + idx];
    }
    for (int idx = tid; idx < 64 * DMO; idx += 256) sxn[idx] = g_xn[t0 * DMO + idx];
    for (int idx = tid; idx < DM * DMO; idx += 256) {
        int c = idx >> 6, i = idx & 63;
        swpT[i * 129 + c] = Wwp[idx];
    }
    for (int idx = tid; idx < DMO * DM; idx += 256) {
        int o = idx >> 7, c = idx & 127;
        sopT[c * 65 + o] = Wop[idx];
    }
    __syncthreads();
    int tx = tid & 31, ty = tid >> 5;
    {
        float acc[8][4] = {};
        for (int i = 0; i < DMO; ++i) {
            float wv[4];
            #pragma unroll
            for (int j = 0; j < 4; ++j) wv[j] = swpT[i * 129 + tx + 32 * j];
            #pragma unroll
            for (int r = 0; r < 8; ++r) {
                float xv = sxn[(ty * 8 + r) * DMO + i];
                #pragma unroll
                for (int j = 0; j < 4; ++j) acc[r][j] = fmaf(xv, wv[j], acc[r][j]);
            }
        }
        for (int r = 0; r < 8; ++r)
            for (int j = 0; j < 4; ++j) {
                int c = tx + 32 * j;
                float v = acc[r][j] + bwp[c];
                float w = v / (1.f + __expf(-v));
                smm[(ty * 8 + r) * 130 + c] *= w;
            }
    }
    __syncthreads();
    {
        int t = tid >> 2;
        int ob = (tid & 3) * 16;
        float acc[16] = {};
        for (int c = 0; c < DM; ++c) {
            float pv = smm[t * 130 + c];
            #pragma unroll
            for (int j = 0; j < 16; ++j) acc[j] = fmaf(pv, sopT[c * 65 + ob + j], acc[j]);
        }
        long tg = t0 + t;
        #pragma unroll
        for (int j = 0; j < 16; ++j) {
            int o = ob + j;
            out[tg * DMO + o] = acc[j] + bop[o] + x[tg * DMO + o];
        }
    }
}

// ---------------- launch -----------------------------------------------------------
extern "C" void kernel_launch(void* const* d_in, const int* in_sizes, int n_in,
                              void* d_out, int out_size) {
    const float* x    = (const float*)d_in[0];
    const float* wn1  = (const float*)d_in[1];
    const float* wn2  = (const float*)d_in[2];
    const float* Wip  = (const float*)d_in[3];
    const float* bip  = (const float*)d_in[4];
    const float* Wfp  = (const float*)d_in[5];
    const float* bfp  = (const float*)d_in[6];
    const float* Wwp  = (const float*)d_in[7];
    const float* bwp  = (const float*)d_in[8];
    const float* Wop  = (const float*)d_in[9];
    const float* bop  = (const float*)d_in[10];
    const float* Win  = (const float*)d_in[11];
    const float* cw   = (const float*)d_in[12];
    const float* cb   = (const float*)d_in[13];
    const float* Xp   = (const float*)d_in[14];
    const float* Wdt  = (const float*)d_in[15];
    const float* bdt  = (const float*)d_in[16];
    const float* Alog = (const float*)d_in[17];
    const float* Dpar = (const float*)d_in[18];
    const float* Wmo  = (const float*)d_in[19];
    float* out = (float*)d_out;

    const int SM_K1 = (64 * 64 + 64 * 129 + 64) * 4;
    const int SM_K2 = (64 * 128 + 128 * 129) * 4;
    const int SM_K4 = (64 * 257 + 256 * 41 + 64 * 40) * 4;
    const int SM_K6 = (256 * 64 + 256 * 129) * 4;
    const int SM_K7 = (64 * 130 + 64 * 64 + 64 * 129 + 128 * 65) * 4;

    cudaFuncSetAttribute(k_rms_u,   cudaFuncAttributeMaxDynamicSharedMemorySize, SM_K1);
    cudaFuncSetAttribute(k_inproj,  cudaFuncAttributeMaxDynamicSharedMemorySize, SM_K2);
    cudaFuncSetAttribute(k_xproj,   cudaFuncAttributeMaxDynamicSharedMemorySize, SM_K4);
    cudaFuncSetAttribute(k_outproj, cudaFuncAttributeMaxDynamicSharedMemorySize, SM_K6);
    cudaFuncSetAttribute(k_final,   cudaFuncAttributeMaxDynamicSharedMemorySize, SM_K7);

    k_combine<<<1, 256>>>(Wfp, Wip, bip, bfp);
    k_rms_u<<<TOK / 64, 256, SM_K1>>>(x, wn1);
    k_inproj<<<dim3(TOK / 64, 4), 256, SM_K2>>>(Win);
    k_conv<<<TOK, DI>>>(cw, cb);
    k_xproj<<<TOK / 64, 256, SM_K4>>>(Xp, Wdt, bdt);
    k_scan1<<<NUNIT / 16, 256>>>(Alog);
    k_scan2<<<64, 256>>>();
    k_scan3<<<NUNIT / 16, 256>>>(Alog, Dpar);
    k_outproj<<<TOK / 64, 256, SM_K6>>>(Wmo, wn2);
    k_final<<<TOK / 64, 256, SM_K7>>>(Wwp, bwp, Wop, bop, x, out);
}

// round 3
// speedup vs baseline: 4.7164x; 1.1896x over previous
#include <cuda_runtime.h>

#define TOK 16384
#define LSEQ 4096
#define NB 4
#define DMO 64      // input/output dim D
#define DM 128      // d_model of mamba (2D)
#define DI 256      // d_inner
#define DS 16       // d_state
#define DTR 8       // dt_rank
#define NCH 1024    // NB * DI channels
#define CHK 64      // chunk length
#define NG (LSEQ / CHK)   // 64 chunks
#define NUNIT (NCH * NG)  // 65536 units

// ---------------- scratch (device globals; no runtime allocation) ----------------
// NOTE: xraw / xc / zs / delta are CHANNEL-MAJOR: [(b*DI + d) * LSEQ + l]
__device__ float g_Wu[DM * DMO];    // combined W_fp @ W_ip
__device__ float g_bu[DM];
__device__ float g_xn[TOK * DMO];   // rmsnorm1(x), token-major
__device__ float g_u[TOK * DM];     // mamba input u, token-major
__device__ float g_xraw[NCH * LSEQ];
__device__ float g_xc[NCH * LSEQ];
__device__ float g_zs[NCH * LSEQ];
__device__ float g_delta[NCH * LSEQ];
__device__ float g_Bm[TOK * DS];    // token-major (lane-coalesced over s)
__device__ float g_Cm[TOK * DS];
__device__ float g_y[NCH * LSEQ];   // gated scan output, channel-major
__device__ float g_m[TOK * DM];     // rmsnorm2(mamba_out) + u
__device__ float g_P[NUNIT * DS];
__device__ float g_q[NUNIT * DS];
__device__ float g_hin[NUNIT * DS];

// ---------------- K0: compose W_u = W_fp @ W_ip, b_u = W_fp@b_ip + b_fp ----------
__global__ void k_combine(const float* __restrict__ Wfp, const float* __restrict__ Wip,
                          const float* __restrict__ bip, const float* __restrict__ bfp) {
    int idx = blockIdx.x * 256 + threadIdx.x;   // grid 32 -> 8192 = DM*DMO
    int o = idx / DMO, i = idx % DMO;
    float s = 0.f;
    for (int k = 0; k < DM; ++k) s = fmaf(Wfp[o * DM + k], Wip[k * DMO + i], s);
    g_Wu[idx] = s;
    if (blockIdx.x == 0 && threadIdx.x < DM) {
        int t = threadIdx.x;
        float sb = bfp[t];
        for (int k = 0; k < DM; ++k) sb = fmaf(Wfp[t * DM + k], bip[k], sb);
        g_bu[t] = sb;
    }
}

// ---------------- K1: rmsnorm1 + u = W_u @ xn + b_u (64 tokens / block) ----------
__global__ void k_rms_u(const float* __restrict__ x, const float* __restrict__ wn1) {
    extern __shared__ float sm[];
    float* sx  = sm;                 // 64*64 normalized x
    float* swT = sm + 64 * DMO;      // [i][o] padded 129
    float* ssc = swT + DMO * 129;    // 64 scales
    int tid = threadIdx.x;
    long t0 = (long)blockIdx.x * 64;

    for (int idx = tid; idx < 64 * DMO; idx += 256) sx[idx] = x[t0 * DMO + idx];
    __syncthreads();
    if (tid < 64) {
        float ss = 0.f;
        for (int i = 0; i < DMO; ++i) { float v = sx[tid * DMO + i]; ss = fmaf(v, v, ss); }
        ssc[tid] = rsqrtf(ss * (1.f / DMO) + 1e-5f);
    }
    __syncthreads();
    for (int idx = tid; idx < 64 * DMO; idx += 256) {
        int t = idx / DMO, i = idx % DMO;
        float v = sx[idx] * ssc[t] * wn1[i];
        sx[idx] = v;
        g_xn[t0 * DMO + idx] = v;
    }
    for (int idx = tid; idx < DM * DMO; idx += 256) {
        int o = idx / DMO, i = idx % DMO;
        swT[i * 129 + o] = g_Wu[idx];
    }
    __syncthreads();
    int tx = tid & 31, ty = tid >> 5;
    float acc[8][4] = {};
    for (int i = 0; i < DMO; ++i) {
        float wv[4];
        #pragma unroll
        for (int j = 0; j < 4; ++j) wv[j] = swT[i * 129 + tx + 32 * j];
        #pragma unroll
        for (int r = 0; r < 8; ++r) {
            float xv = sx[(ty * 8 + r) * DMO + i];
            #pragma unroll
            for (int j = 0; j < 4; ++j) acc[r][j] = fmaf(xv, wv[j], acc[r][j]);
        }
    }
    for (int r = 0; r < 8; ++r)
        for (int j = 0; j < 4; ++j) {
            int t = ty * 8 + r, o = tx + 32 * j;
            g_u[(t0 + t) * DM + o] = acc[r][j] + g_bu[o];
        }
}

// ---------------- K2: xz = in_proj @ u ; xraw / silu(z) in channel-major ---------
__global__ void k_inproj(const float* __restrict__ Win) {
    extern __shared__ float sm[];
    float* su  = sm;              // 64*128 [t][i]
    float* swT = sm + 64 * DM;    // [i][e] padded 129; reused as stage [e][t] 128*65
    int tid = threadIdx.x;
    long t0 = (long)blockIdx.x * 64;
    int e0 = blockIdx.y * 128;
    int b = (int)(t0 >> 12);
    int l0 = (int)(t0 & (LSEQ - 1));

    for (int idx = tid; idx < 64 * DM; idx += 256) su[idx] = g_u[t0 * DM + idx];
    for (int idx = tid; idx < 128 * DM; idx += 256) {
        int e = idx >> 7, i = idx & 127;
        swT[i * 129 + e] = Win[(long)(e0 + e) * DM + i];
    }
    __syncthreads();
    int tx = tid & 31, ty = tid >> 5;
    float acc[8][4] = {};
    for (int i = 0; i < DM; ++i) {
        float wv[4];
        #pragma unroll
        for (int j = 0; j < 4; ++j) wv[j] = swT[i * 129 + tx + 32 * j];
        #pragma unroll
        for (int r = 0; r < 8; ++r) {
            float xv = su[(ty * 8 + r) * DM + i];
            #pragma unroll
            for (int j = 0; j < 4; ++j) acc[r][j] = fmaf(xv, wv[j], acc[r][j]);
        }
    }
    __syncthreads();   // swT dead -> reuse as [e][t] stage
    for (int r = 0; r < 8; ++r)
        #pragma unroll
        for (int j = 0; j < 4; ++j) {
            int t = ty * 8 + r, e = tx + 32 * j;
            swT[e * 65 + t] = acc[r][j];
        }
    __syncthreads();
    bool isz = (e0 >= DI);
    float* dst = isz ? g_zs : g_xraw;
    int dbase = isz ? (e0 - DI) : e0;
    for (int idx = tid; idx < 128 * 64; idx += 256) {
        int e = idx >> 6, t = idx & 63;
        float v = swT[e * 65 + t];
        if (isz) v = v / (1.f + __expf(-v));
        dst[(long)(b * DI + dbase + e) * LSEQ + l0 + t] = v;
    }
}

// ---------------- K3: causal depthwise conv (k=4) + bias + silu, contiguous ------
__global__ void k_conv(const float* __restrict__ cw, const float* __restrict__ cb) {
    int ch = blockIdx.x;             // 0..1023
    int d = ch & (DI - 1);
    const float* src = g_xraw + (long)ch * LSEQ;
    float* dst = g_xc + (long)ch * LSEQ;
    float w0 = cw[d * 4 + 0], w1 = cw[d * 4 + 1], w2 = cw[d * 4 + 2], w3 = cw[d * 4 + 3];
    float bb = cb[d];
    for (int l = threadIdx.x; l < LSEQ; l += 256) {
        float acc = bb;
        acc = fmaf(w3, src[l], acc);
        if (l >= 1) acc = fmaf(w2, src[l - 1], acc);
        if (l >= 2) acc = fmaf(w1, src[l - 2], acc);
        if (l >= 3) acc = fmaf(w0, src[l - 3], acc);
        dst[l] = acc / (1.f + __expf(-acc));
    }
}

// ---------------- K4: x_dbl = x_proj @ x ; B,C split ; delta = softplus(...) -----
__global__ void k_xproj(const float* __restrict__ Xp, const float* __restrict__ Wdt,
                        const float* __restrict__ bdt) {
    extern __shared__ float sm[];
    float* sx   = sm;                    // phase1: [t][k] 64*257 ; phase2: sdel [d][t] 256*65
    float* spT  = sm + 16640;            // [k][e] padded 41
    float* sdbl = spT + 256 * 41;        // 64*40
    int tid = threadIdx.x;
    long t0 = (long)blockIdx.x * 64;
    int b = (int)(t0 >> 12);
    int l0 = (int)(t0 & (LSEQ - 1));

    for (int idx = tid; idx < 64 * DI; idx += 256) {
        int d = idx >> 6, t = idx & 63;
        sx[t * 257 + d] = g_xc[(long)(b * DI + d) * LSEQ + l0 + t];
    }
    for (int idx = tid; idx < 40 * DI; idx += 256) {
        int e = idx >> 8, k = idx & 255;
        spT[k * 41 + e] = Xp[idx];
    }
    __syncthreads();
    {
        int t = tid >> 2, eb = (tid & 3) * 10;
        float acc[10] = {};
        for (int k = 0; k < DI; ++k) {
            float xv = sx[t * 257 + k];
            #pragma unroll
            for (int e = 0; e < 10; ++e) acc[e] = fmaf(xv, spT[k * 41 + eb + e], acc[e]);
        }
        for (int e = 0; e < 10; ++e) sdbl[t * 40 + eb + e] = acc[e];
    }
    __syncthreads();
    for (int idx = tid; idx < 64 * DS; idx += 256) {
        int t = idx >> 4, s = idx & 15;
        g_Bm[(t0 + t) * DS + s] = sdbl[t * 40 + 8 + s];
        g_Cm[(t0 + t) * DS + s] = sdbl[t * 40 + 24 + s];
    }
    {   // delta -> smem stage (sx region now dead)
        int d = tid;
        float wr[8];
        #pragma unroll
        for (int r = 0; r < 8; ++r) wr[r] = Wdt[d * 8 + r];
        float bb = bdt[d];
        for (int t = 0; t < 64; ++t) {
            float pre = bb;
            #pragma unroll
            for (int r = 0; r < 8; ++r) pre = fmaf(sdbl[t * 40 + r], wr[r], pre);
            float sp = (pre > 20.f) ? pre : log1pf(__expf(pre));
            sx[d * 65 + t] = sp;
        }
    }
    __syncthreads();
    for (int idx = tid; idx < DI * 64; idx += 256) {
        int d = idx >> 6, t = idx & 63;
        g_delta[(long)(b * DI + d) * LSEQ + l0 + t] = sx[d * 65 + t];
    }
}

// ---------------- K5a: per-chunk decay product P and local state q ----------------
__global__ void k_scan1(const float* __restrict__ Alog) {
    int u = threadIdx.x >> 4;
    int s = threadIdx.x & 15;
    int unit = blockIdx.x * 16 + u;
    int g = unit & (NG - 1);
    int ch = unit >> 6;              // b*DI + d
    int b = ch >> 8, d = ch & 255;
    float Aval = -__expf(Alog[d * DS + s]);
    const float* pd = g_delta + (long)ch * LSEQ + g * CHK;
    const float* px = g_xc    + (long)ch * LSEQ + g * CHK;
    const float* pB = g_Bm    + ((long)b * LSEQ + g * CHK) * DS + s;
    float P = 1.f, q = 0.f;
    #pragma unroll 8
    for (int t = 0; t < CHK; ++t) {
        float dv = pd[t];
        float xv = px[t];
        float Bv = pB[t * DS];
        float a = __expf(dv * Aval);
        P *= a;
        q = fmaf(a, q, dv * xv * Bv);
    }
    long idx = (long)unit * DS + s;
    g_P[idx] = P;
    g_q[idx] = q;
}

// ---------------- K5b: propagate h_in across chunks (per channel-state) ----------
__global__ void k_scan2() {
    int tid = blockIdx.x * 256 + threadIdx.x;   // 0..16383 = channel*16 + state
    int ch = tid >> 4, s = tid & 15;
    float h = 0.f;
    long base = (long)ch * NG * DS + s;
    #pragma unroll 8
    for (int g = 0; g < NG; ++g) {
        long idx = base + (long)g * DS;
        g_hin[idx] = h;
        h = fmaf(g_P[idx], h, g_q[idx]);
    }
}

// ---------------- K5c: local scan from h_in, y = (C.h + x*D) * silu(z) -----------
__global__ void k_scan3(const float* __restrict__ Alog, const float* __restrict__ Dp_) {
    __shared__ float ybuf[16 * CHK];
    int u = threadIdx.x >> 4;
    int s = threadIdx.x & 15;
    int unit = blockIdx.x * 16 + u;
    int g = unit & (NG - 1);
    int ch = unit >> 6;
    int b = ch >> 8, d = ch & 255;
    float Aval = -__expf(Alog[d * DS + s]);
    float Dp = Dp_[d];
    const float* pd = g_delta + (long)ch * LSEQ + g * CHK;
    const float* px = g_xc    + (long)ch * LSEQ + g * CHK;
    const float* pz = g_zs    + (long)ch * LSEQ + g * CHK;
    const float* pB = g_Bm    + ((long)b * LSEQ + g * CHK) * DS + s;
    const float* pC = g_Cm    + ((long)b * LSEQ + g * CHK) * DS + s;
    float h = g_hin[(long)unit * DS + s];
    #pragma unroll 4
    for (int t = 0; t < CHK; ++t) {
        float dv = pd[t];
        float xv = px[t];
        float Bv = pB[t * DS];
        float Cv = pC[t * DS];
        float a = __expf(dv * Aval);
        h = fmaf(a, h, dv * xv * Bv);
        float p = h * Cv;
        p += __shfl_xor_sync(0xffffffffu, p, 8);
        p += __shfl_xor_sync(0xffffffffu, p, 4);
        p += __shfl_xor_sync(0xffffffffu, p, 2);
        p += __shfl_xor_sync(0xffffffffu, p, 1);
        if (s == 0) ybuf[u * CHK + t] = (p + xv * Dp) * pz[t];
    }
    __syncthreads();
    float* py = g_y + (long)ch * LSEQ + (long)(blockIdx.x & 3) * 1024;
    for (int i = threadIdx.x; i < 16 * CHK; i += 256) py[i] = ybuf[i];
}

// ---------------- K6: m = rmsnorm2(mamba_out @ y) + u -----------------------------
__global__ void k_outproj(const float* __restrict__ Wmo, const float* __restrict__ wn2) {
    extern __shared__ float sm[];
    float* syT = sm;               // [k][tl] 256*64
    float* swT = sm + DI * 64;     // [k][o] padded 129
    int tid = threadIdx.x;
    long t0 = (long)blockIdx.x * 64;
    int b = (int)(t0 >> 12);
    int lpos = (int)(t0 & (LSEQ - 1));

    for (int idx = tid; idx < DI * 64; idx += 256) {
        int k = idx >> 6, tl = idx & 63;
        syT[idx] = g_y[(long)(b * DI + k) * LSEQ + lpos + tl];
    }
    for (int idx = tid; idx < DM * DI; idx += 256) {
        int o = idx >> 8, k = idx & 255;
        swT[k * 129 + o] = Wmo[idx];
    }
    __syncthreads();
    int tx = tid & 31, ty = tid >> 5;
    float acc[8][4] = {};
    for (int k = 0; k < DI; ++k) {
        float wv[4];
        #pragma unroll
        for (int j = 0; j < 4; ++j) wv[j] = swT[k * 129 + tx + 32 * j];
        #pragma unroll
        for (int r = 0; r < 8; ++r) {
            float yv = syT[k * 64 + ty * 8 + r];
            #pragma unroll
            for (int j = 0; j < 4; ++j) acc[r][j] = fmaf(yv, wv[j], acc[r][j]);
        }
    }
    for (int r = 0; r < 8; ++r) {
        float ss = 0.f;
        #pragma unroll
        for (int j = 0; j < 4; ++j) ss = fmaf(acc[r][j], acc[r][j], ss);
        #pragma unroll
        for (int off = 16; off >= 1; off >>= 1) ss += __shfl_xor_sync(0xffffffffu, ss, off);
        float sc = rsqrtf(ss * (1.f / DM) + 1e-5f);
        long t = t0 + ty * 8 + r;
        #pragma unroll
        for (int j = 0; j < 4; ++j) {
            int o = tx + 32 * j;
            g_m[t * DM + o] = acc[r][j] * sc * wn2[o] + g_u[t * DM + o];
        }
    }
}

// ---------------- K7: w = swish(W_wp@xn+b) ; out = W_op@(w*m)+b + x ---------------
__global__ void k_final(const float* __restrict__ Wwp, const float* __restrict__ bwp,
                        const float* __restrict__ Wop, const float* __restrict__ bop,
                        const float* __restrict__ x, float* __restrict__ out) {
    extern __shared__ float sm[];
    float* smm  = sm;                      // 64*130 (m, then p = w*m)
    float* sxn  = smm + 64 * 130;          // 64*64
    float* swpT = sxn + 64 * DMO;          // [i][c] padded 129
    float* sopT = swpT + DMO * 129;        // [c][o] padded 65
    int tid = threadIdx.x;
    long t0 = (long)blockIdx.x * 64;

    for (int idx = tid; idx < 64 * DM; idx += 256) {
        int t = idx >> 7, c = idx & 127;
        smm[t * 130 + c] = g_m[t0 * DM + idx];
    }
    for (int idx = tid; idx < 64 * DMO; idx += 256) sxn[idx] = g_xn[t0 * DMO + idx];
    for (int idx = tid; idx < DM * DMO; idx += 256) {
        int c = idx >> 6, i = idx & 63;
        swpT[i * 129 + c] = Wwp[idx];
    }
    for (int idx = tid; idx < DMO * DM; idx += 256) {
        int o = idx >> 7, c = idx & 127;
        sopT[c * 65 + o] = Wop[idx];
    }
    __syncthreads();
    int tx = tid & 31, ty = tid >> 5;
    {
        float acc[8][4] = {};
        for (int i = 0; i < DMO; ++i) {
            float wv[4];
            #pragma unroll
            for (int j = 0; j < 4; ++j) wv[j] = swpT[i * 129 + tx + 32 * j];
            #pragma unroll
            for (int r = 0; r < 8; ++r) {
                float xv = sxn[(ty * 8 + r) * DMO + i];
                #pragma unroll
                for (int j = 0; j < 4; ++j) acc[r][j] = fmaf(xv, wv[j], acc[r][j]);
            }
        }
        for (int r = 0; r < 8; ++r)
            for (int j = 0; j < 4; ++j) {
                int c = tx + 32 * j;
                float v = acc[r][j] + bwp[c];
                float w = v / (1.f + __expf(-v));
                smm[(ty * 8 + r) * 130 + c] *= w;
            }
    }
    __syncthreads();
    {
        int t = tid >> 2;
        int ob = (tid & 3) * 16;
        float acc[16] = {};
        for (int c = 0; c < DM; ++c) {
            float pv = smm[t * 130 + c];
            #pragma unroll
            for (int j = 0; j < 16; ++j) acc[j] = fmaf(pv, sopT[c * 65 + ob + j], acc[j]);
        }
        long tg = t0 + t;
        #pragma unroll
        for (int j = 0; j < 16; ++j) {
            int o = ob + j;
            out[tg * DMO + o] = acc[j] + bop[o] + x[tg * DMO + o];
        }
    }
}

// ---------------- launch -----------------------------------------------------------
extern "C" void kernel_launch(void* const* d_in, const int* in_sizes, int n_in,
                              void* d_out, int out_size) {
    const float* x    = (const float*)d_in[0];
    const float* wn1  = (const float*)d_in[1];
    const float* wn2  = (const float*)d_in[2];
    const float* Wip  = (const float*)d_in[3];
    const float* bip  = (const float*)d_in[4];
    const float* Wfp  = (const float*)d_in[5];
    const float* bfp  = (const float*)d_in[6];
    const float* Wwp  = (const float*)d_in[7];
    const float* bwp  = (const float*)d_in[8];
    const float* Wop  = (const float*)d_in[9];
    const float* bop  = (const float*)d_in[10];
    const float* Win  = (const float*)d_in[11];
    const float* cw   = (const float*)d_in[12];
    const float* cb   = (const float*)d_in[13];
    const float* Xp   = (const float*)d_in[14];
    const float* Wdt  = (const float*)d_in[15];
    const float* bdt  = (const float*)d_in[16];
    const float* Alog = (const float*)d_in[17];
    const float* Dpar = (const float*)d_in[18];
    const float* Wmo  = (const float*)d_in[19];
    float* out = (float*)d_out;

    const int SM_K1 = (64 * 64 + 64 * 129 + 64) * 4;
    const int SM_K2 = (64 * 128 + 128 * 129) * 4;
    const int SM_K4 = (16640 + 256 * 41 + 64 * 40) * 4;
    const int SM_K6 = (256 * 64 + 256 * 129) * 4;
    const int SM_K7 = (64 * 130 + 64 * 64 + 64 * 129 + 128 * 65) * 4;

    cudaFuncSetAttribute(k_rms_u,   cudaFuncAttributeMaxDynamicSharedMemorySize, SM_K1);
    cudaFuncSetAttribute(k_inproj,  cudaFuncAttributeMaxDynamicSharedMemorySize, SM_K2);
    cudaFuncSetAttribute(k_xproj,   cudaFuncAttributeMaxDynamicSharedMemorySize, SM_K4);
    cudaFuncSetAttribute(k_outproj, cudaFuncAttributeMaxDynamicSharedMemorySize, SM_K6);
    cudaFuncSetAttribute(k_final,   cudaFuncAttributeMaxDynamicSharedMemorySize, SM_K7);

    k_combine<<<32, 256>>>(Wfp, Wip, bip, bfp);
    k_rms_u<<<TOK / 64, 256, SM_K1>>>(x, wn1);
    k_inproj<<<dim3(TOK / 64, 4), 256, SM_K2>>>(Win);
    k_conv<<<NCH, 256>>>(cw, cb);
    k_xproj<<<TOK / 64, 256, SM_K4>>>(Xp, Wdt, bdt);
    k_scan1<<<NUNIT / 16, 256>>>(Alog);
    k_scan2<<<64, 256>>>();
    k_scan3<<<NUNIT / 16, 256>>>(Alog, Dpar);
    k_outproj<<<TOK / 64, 256, SM_K6>>>(Wmo, wn2);
    k_final<<<TOK / 64, 256, SM_K7>>>(Wwp, bwp, Wop, bop, x, out);
}

// round 4
// speedup vs baseline: 5.6264x; 1.1929x over previous
#include <cuda_runtime.h>

#define TOK 16384
#define LSEQ 4096
#define NB 4
#define DMO 64      // input/output dim D
#define DM 128      // d_model of mamba (2D)
#define DI 256      // d_inner
#define DS 16       // d_state
#define DTR 8       // dt_rank
#define NCH 1024    // NB * DI channels
#define CHK 64      // chunk length
#define NG (LSEQ / CHK)   // 64 chunks
#define NUNIT (NCH * NG)  // 65536 units

typedef unsigned long long ull;

__device__ __forceinline__ ull pk2(float a, float b) {
    ull r; asm("mov.b64 %0, {%1, %2};" : "=l"(r) : "f"(a), "f"(b)); return r;
}
__device__ __forceinline__ void fma2(ull& d, ull a, ull b) {
    asm("fma.rn.f32x2 %0, %1, %2, %3;" : "=l"(d) : "l"(a), "l"(b), "l"(d));
}
__device__ __forceinline__ float2 upk(ull v) {
    float2 r; asm("mov.b64 {%0, %1}, %2;" : "=f"(r.x), "=f"(r.y) : "l"(v)); return r;
}

// ---------------- scratch ----------------
// xraw / xc / zs / delta / y are CHANNEL-MAJOR: [(b*DI + d) * LSEQ + l]
__device__ float g_Wu[DM * DMO];
__device__ float g_bu[DM];
__device__ float g_xn[TOK * DMO];
__device__ float g_u[TOK * DM];
__device__ float g_xraw[NCH * LSEQ];
__device__ float g_xc[NCH * LSEQ];
__device__ float g_zs[NCH * LSEQ];
__device__ float g_delta[NCH * LSEQ];
__device__ float g_Bm[TOK * DS];
__device__ float g_Cm[TOK * DS];
__device__ float g_y[NCH * LSEQ];
__device__ float g_m[TOK * DM];
__device__ float g_P[NUNIT * DS];
__device__ float g_q[NUNIT * DS];
__device__ float g_hin[NUNIT * DS];

// ---------------- K0: compose W_u = W_fp @ W_ip, b_u = W_fp@b_ip + b_fp ----------
__global__ void k_combine(const float* __restrict__ Wfp, const float* __restrict__ Wip,
                          const float* __restrict__ bip, const float* __restrict__ bfp) {
    int idx = blockIdx.x * 256 + threadIdx.x;
    int o = idx / DMO, i = idx % DMO;
    float s = 0.f;
    for (int k = 0; k < DM; ++k) s = fmaf(Wfp[o * DM + k], Wip[k * DMO + i], s);
    g_Wu[idx] = s;
    if (blockIdx.x == 0 && threadIdx.x < DM) {
        int t = threadIdx.x;
        float sb = bfp[t];
        for (int k = 0; k < DM; ++k) sb = fmaf(Wfp[t * DM + k], bip[k], sb);
        g_bu[t] = sb;
    }
}

// ---------------- K1: rmsnorm1 + u = W_u @ xn + b_u ------------------------------
// sx [i][t] 64x68 (transposed), swT [i][o] 64x132, f32x2 GEMM
__global__ void k_rms_u(const float* __restrict__ x, const float* __restrict__ wn1) {
    extern __shared__ float sm[];
    float* sx  = sm;                 // 64*68
    float* swT = sm + 64 * 68;       // 64*132
    float* ssc = swT + 64 * 132;     // 64
    int tid = threadIdx.x;
    long t0 = (long)blockIdx.x * 64;

    for (int idx = tid; idx < 64 * 64; idx += 256) {
        int i = idx & 63, t = idx >> 6;
        sx[i * 68 + t] = x[(t0 + t) * DMO + i];
    }
    for (int idx = tid; idx < DM * DMO; idx += 256) {
        int i = idx & 63, o = idx >> 6;
        swT[i * 132 + o] = g_Wu[o * DMO + i];
    }
    __syncthreads();
    if (tid < 64) {
        float ss = 0.f;
        for (int i = 0; i < DMO; ++i) { float v = sx[i * 68 + tid]; ss = fmaf(v, v, ss); }
        ssc[tid] = rsqrtf(ss * (1.f / DMO) + 1e-5f);
    }
    __syncthreads();
    for (int idx = tid; idx < 64 * 64; idx += 256) {
        int i = idx & 63, t = idx >> 6;
        float v = sx[i * 68 + t] * ssc[t] * wn1[i];
        sx[i * 68 + t] = v;
        g_xn[(t0 + t) * DMO + i] = v;
    }
    __syncthreads();
    int tx = tid & 31, ty = tid >> 5;
    ull acc[4][4] = {};
    for (int i = 0; i < DMO; ++i) {
        float4 w4 = *(const float4*)&swT[i * 132 + (tx << 2)];
        ull wd0 = pk2(w4.x, w4.x), wd1 = pk2(w4.y, w4.y);
        ull wd2 = pk2(w4.z, w4.z), wd3 = pk2(w4.w, w4.w);
        ulonglong2 xa = *(const ulonglong2*)&sx[i * 68 + ty * 8];
        ulonglong2 xb = *(const ulonglong2*)&sx[i * 68 + ty * 8 + 4];
        fma2(acc[0][0], xa.x, wd0); fma2(acc[0][1], xa.x, wd1); fma2(acc[0][2], xa.x, wd2); fma2(acc[0][3], xa.x, wd3);
        fma2(acc[1][0], xa.y, wd0); fma2(acc[1][1], xa.y, wd1); fma2(acc[1][2], xa.y, wd2); fma2(acc[1][3], xa.y, wd3);
        fma2(acc[2][0], xb.x, wd0); fma2(acc[2][1], xb.x, wd1); fma2(acc[2][2], xb.x, wd2); fma2(acc[2][3], xb.x, wd3);
        fma2(acc[3][0], xb.y, wd0); fma2(acc[3][1], xb.y, wd1); fma2(acc[3][2], xb.y, wd2); fma2(acc[3][3], xb.y, wd3);
    }
    float4 bq = *(const float4*)&g_bu[tx << 2];
    #pragma unroll
    for (int p = 0; p < 4; ++p) {
        float2 v0 = upk(acc[p][0]), v1 = upk(acc[p][1]), v2 = upk(acc[p][2]), v3 = upk(acc[p][3]);
        long ta = t0 + ty * 8 + 2 * p, tb = ta + 1;
        float4 lo = make_float4(v0.x + bq.x, v1.x + bq.y, v2.x + bq.z, v3.x + bq.w);
        float4 hi = make_float4(v0.y + bq.x, v1.y + bq.y, v2.y + bq.z, v3.y + bq.w);
        *(float4*)&g_u[ta * DM + (tx << 2)] = lo;
        *(float4*)&g_u[tb * DM + (tx << 2)] = hi;
    }
}

// ---------------- K2: xz = in_proj @ u ; xraw / silu(z), channel-major out --------
__global__ void k_inproj(const float* __restrict__ Win) {
    extern __shared__ float sm[];
    float* su  = sm;              // [i][t] 128*68
    float* swT = sm + 128 * 68;   // [i][e] 128*132; reused as stage [e][t] 128*65
    int tid = threadIdx.x;
    long t0 = (long)blockIdx.x * 64;
    int e0 = blockIdx.y * 128;
    int b = (int)(t0 >> 12);
    int l0 = (int)(t0 & (LSEQ - 1));

    for (int idx = tid; idx < 64 * DM; idx += 256) {
        int i = idx & 127, t = idx >> 7;
        su[i * 68 + t] = g_u[(t0 + t) * DM + i];
    }
    for (int idx = tid; idx < 128 * DM; idx += 256) {
        int i = idx & 127, e = idx >> 7;
        swT[i * 132 + e] = Win[(long)(e0 + e) * DM + i];
    }
    __syncthreads();
    int tx = tid & 31, ty = tid >> 5;
    ull acc[4][4] = {};
    for (int i = 0; i < DM; ++i) {
        float4 w4 = *(const float4*)&swT[i * 132 + (tx << 2)];
        ull wd0 = pk2(w4.x, w4.x), wd1 = pk2(w4.y, w4.y);
        ull wd2 = pk2(w4.z, w4.z), wd3 = pk2(w4.w, w4.w);
        ulonglong2 xa = *(const ulonglong2*)&su[i * 68 + ty * 8];
        ulonglong2 xb = *(const ulonglong2*)&su[i * 68 + ty * 8 + 4];
        fma2(acc[0][0], xa.x, wd0); fma2(acc[0][1], xa.x, wd1); fma2(acc[0][2], xa.x, wd2); fma2(acc[0][3], xa.x, wd3);
        fma2(acc[1][0], xa.y, wd0); fma2(acc[1][1], xa.y, wd1); fma2(acc[1][2], xa.y, wd2); fma2(acc[1][3], xa.y, wd3);
        fma2(acc[2][0], xb.x, wd0); fma2(acc[2][1], xb.x, wd1); fma2(acc[2][2], xb.x, wd2); fma2(acc[2][3], xb.x, wd3);
        fma2(acc[3][0], xb.y, wd0); fma2(acc[3][1], xb.y, wd1); fma2(acc[3][2], xb.y, wd2); fma2(acc[3][3], xb.y, wd3);
    }
    __syncthreads();   // swT dead -> stage [e][t]
    float* stage = swT;
    #pragma unroll
    for (int p = 0; p < 4; ++p)
        #pragma unroll
        for (int j = 0; j < 4; ++j) {
            float2 v = upk(acc[p][j]);
            int e = (tx << 2) + j, t = ty * 8 + 2 * p;
            stage[e * 65 + t] = v.x;
            stage[e * 65 + t + 1] = v.y;
        }
    __syncthreads();
    bool isz = (e0 >= DI);
    float* dst = isz ? g_zs : g_xraw;
    int dbase = isz ? (e0 - DI) : e0;
    for (int idx = tid; idx < 128 * 64; idx += 256) {
        int e = idx >> 6, t = idx & 63;
        float v = stage[e * 65 + t];
        if (isz) v = v / (1.f + __expf(-v));
        dst[(long)(b * DI + dbase + e) * LSEQ + l0 + t] = v;
    }
}

// ---------------- K3: causal depthwise conv (k=4) + bias + silu ------------------
__global__ void k_conv(const float* __restrict__ cw, const float* __restrict__ cb) {
    int ch = blockIdx.x;
    int d = ch & (DI - 1);
    const float* src = g_xraw + (long)ch * LSEQ;
    float* dst = g_xc + (long)ch * LSEQ;
    float w0 = cw[d * 4 + 0], w1 = cw[d * 4 + 1], w2 = cw[d * 4 + 2], w3 = cw[d * 4 + 3];
    float bb = cb[d];
    for (int l = threadIdx.x; l < LSEQ; l += 256) {
        float acc = bb;
        acc = fmaf(w3, src[l], acc);
        if (l >= 1) acc = fmaf(w2, src[l - 1], acc);
        if (l >= 2) acc = fmaf(w1, src[l - 2], acc);
        if (l >= 3) acc = fmaf(w0, src[l - 3], acc);
        dst[l] = acc / (1.f + __expf(-acc));
    }
}

// ---------------- K4: x_dbl = x_proj @ x ; B,C split ; delta = softplus(...) -----
__global__ void k_xproj(const float* __restrict__ Xp, const float* __restrict__ Wdt,
                        const float* __restrict__ bdt) {
    extern __shared__ float sm[];
    float* sx   = sm;                    // phase1: [t][k] 64*260 ; phase2: sdel [d][t] 256*65
    float* spTT = sm + 16640;            // [e][k] 40*260
    float* sdbl = spTT + 40 * 260;       // 64*40
    int tid = threadIdx.x;
    long t0 = (long)blockIdx.x * 64;
    int b = (int)(t0 >> 12);
    int l0 = (int)(t0 & (LSEQ - 1));

    for (int idx = tid; idx < 64 * DI; idx += 256) {
        int t = idx & 63, d = idx >> 6;
        sx[t * 260 + d] = g_xc[(long)(b * DI + d) * LSEQ + l0 + t];
    }
    for (int idx = tid; idx < 40 * DI; idx += 256) {
        int k = idx & 255, e = idx >> 8;
        spTT[e * 260 + k] = Xp[e * DI + k];
    }
    __syncthreads();
    {
        int t = tid >> 2, eb = (tid & 3) * 10;
        float acc[10] = {};
        for (int k = 0; k < DI; k += 4) {
            float4 xv = *(const float4*)&sx[t * 260 + k];
            #pragma unroll
            for (int e = 0; e < 10; ++e) {
                float4 wv = *(const float4*)&spTT[(eb + e) * 260 + k];
                acc[e] = fmaf(xv.x, wv.x, fmaf(xv.y, wv.y, fmaf(xv.z, wv.z, fmaf(xv.w, wv.w, acc[e]))));
            }
        }
        #pragma unroll
        for (int e = 0; e < 10; ++e) sdbl[t * 40 + eb + e] = acc[e];
    }
    __syncthreads();
    for (int idx = tid; idx < 64 * DS; idx += 256) {
        int t = idx >> 4, s = idx & 15;
        g_Bm[(t0 + t) * DS + s] = sdbl[t * 40 + 8 + s];
        g_Cm[(t0 + t) * DS + s] = sdbl[t * 40 + 24 + s];
    }
    {
        int d = tid;
        float wr[8];
        #pragma unroll
        for (int r = 0; r < 8; ++r) wr[r] = Wdt[d * 8 + r];
        float bb = bdt[d];
        for (int t = 0; t < 64; ++t) {
            float pre = bb;
            #pragma unroll
            for (int r = 0; r < 8; ++r) pre = fmaf(sdbl[t * 40 + r], wr[r], pre);
            float sp = (pre > 20.f) ? pre : log1pf(__expf(pre));
            sx[d * 65 + t] = sp;
        }
    }
    __syncthreads();
    for (int idx = tid; idx < DI * 64; idx += 256) {
        int d = idx >> 6, t = idx & 63;
        g_delta[(long)(b * DI + d) * LSEQ + l0 + t] = sx[d * 65 + t];
    }
}

// ---------------- K5a: per-chunk decay product P and local state q ----------------
__global__ void k_scan1(const float* __restrict__ Alog) {
    int u = threadIdx.x >> 4;
    int s = threadIdx.x & 15;
    int unit = blockIdx.x * 16 + u;
    int g = unit & (NG - 1);
    int ch = unit >> 6;
    int b = ch >> 8, d = ch & 255;
    float Aval = -__expf(Alog[d * DS + s]);
    const float* pd = g_delta + (long)ch * LSEQ + g * CHK;
    const float* px = g_xc    + (long)ch * LSEQ + g * CHK;
    const float* pB = g_Bm    + ((long)b * LSEQ + g * CHK) * DS + s;
    float P = 1.f, q = 0.f;
    #pragma unroll 8
    for (int t = 0; t < CHK; ++t) {
        float dv = pd[t];
        float xv = px[t];
        float Bv = pB[t * DS];
        float a = __expf(dv * Aval);
        P *= a;
        q = fmaf(a, q, dv * xv * Bv);
    }
    long idx = (long)unit * DS + s;
    g_P[idx] = P;
    g_q[idx] = q;
}

// ---------------- K5b: propagate h_in across chunks ------------------------------
__global__ void k_scan2() {
    int tid = blockIdx.x * 256 + threadIdx.x;
    int ch = tid >> 4, s = tid & 15;
    float h = 0.f;
    long base = (long)ch * NG * DS + s;
    #pragma unroll 8
    for (int g = 0; g < NG; ++g) {
        long idx = base + (long)g * DS;
        g_hin[idx] = h;
        h = fmaf(g_P[idx], h, g_q[idx]);
    }
}

// ---------------- K5c: local scan from h_in, y = (C.h + x*D) * silu(z) -----------
__global__ void k_scan3(const float* __restrict__ Alog, const float* __restrict__ Dp_) {
    __shared__ float ybuf[16 * CHK];
    int u = threadIdx.x >> 4;
    int s = threadIdx.x & 15;
    int unit = blockIdx.x * 16 + u;
    int g = unit & (NG - 1);
    int ch = unit >> 6;
    int b = ch >> 8, d = ch & 255;
    float Aval = -__expf(Alog[d * DS + s]);
    float Dp = Dp_[d];
    const float* pd = g_delta + (long)ch * LSEQ + g * CHK;
    const float* px = g_xc    + (long)ch * LSEQ + g * CHK;
    const float* pz = g_zs    + (long)ch * LSEQ + g * CHK;
    const float* pB = g_Bm    + ((long)b * LSEQ + g * CHK) * DS + s;
    const float* pC = g_Cm    + ((long)b * LSEQ + g * CHK) * DS + s;
    float h = g_hin[(long)unit * DS + s];
    #pragma unroll 4
    for (int t = 0; t < CHK; ++t) {
        float dv = pd[t];
        float xv = px[t];
        float Bv = pB[t * DS];
        float Cv = pC[t * DS];
        float a = __expf(dv * Aval);
        h = fmaf(a, h, dv * xv * Bv);
        float p = h * Cv;
        p += __shfl_xor_sync(0xffffffffu, p, 8);
        p += __shfl_xor_sync(0xffffffffu, p, 4);
        p += __shfl_xor_sync(0xffffffffu, p, 2);
        p += __shfl_xor_sync(0xffffffffu, p, 1);
        if (s == 0) ybuf[u * CHK + t] = (p + xv * Dp) * pz[t];
    }
    __syncthreads();
    float* py = g_y + (long)ch * LSEQ + (long)(blockIdx.x & 3) * 1024;
    for (int i = threadIdx.x; i < 16 * CHK; i += 256) py[i] = ybuf[i];
}

// ---------------- K6: m = rmsnorm2(mamba_out @ y) + u -----------------------------
// syT [k][t] 256x68, swT [k][o] 256x132, f32x2 GEMM
__global__ void k_outproj(const float* __restrict__ Wmo, const float* __restrict__ wn2) {
    extern __shared__ float sm[];
    float* syT = sm;               // 256*68
    float* swT = sm + 256 * 68;    // 256*132
    int tid = threadIdx.x;
    long t0 = (long)blockIdx.x * 64;
    int b = (int)(t0 >> 12);
    int lpos = (int)(t0 & (LSEQ - 1));

    for (int idx = tid; idx < DI * 64; idx += 256) {
        int t = idx & 63, k = idx >> 6;
        syT[k * 68 + t] = g_y[(long)(b * DI + k) * LSEQ + lpos + t];
    }
    for (int idx = tid; idx < DM * DI; idx += 256) {
        int k = idx & 255, o = idx >> 8;
        swT[k * 132 + o] = Wmo[o * DI + k];
    }
    __syncthreads();
    int tx = tid & 31, ty = tid >> 5;
    ull acc[4][4] = {};
    for (int k = 0; k < DI; ++k) {
        float4 w4 = *(const float4*)&swT[k * 132 + (tx << 2)];
        ull wd0 = pk2(w4.x, w4.x), wd1 = pk2(w4.y, w4.y);
        ull wd2 = pk2(w4.z, w4.z), wd3 = pk2(w4.w, w4.w);
        ulonglong2 xa = *(const ulonglong2*)&syT[k * 68 + ty * 8];
        ulonglong2 xb = *(const ulonglong2*)&syT[k * 68 + ty * 8 + 4];
        fma2(acc[0][0], xa.x, wd0); fma2(acc[0][1], xa.x, wd1); fma2(acc[0][2], xa.x, wd2); fma2(acc[0][3], xa.x, wd3);
        fma2(acc[1][0], xa.y, wd0); fma2(acc[1][1], xa.y, wd1); fma2(acc[1][2], xa.y, wd2); fma2(acc[1][3], xa.y, wd3);
        fma2(acc[2][0], xb.x, wd0); fma2(acc[2][1], xb.x, wd1); fma2(acc[2][2], xb.x, wd2); fma2(acc[2][3], xb.x, wd3);
        fma2(acc[3][0], xb.y, wd0); fma2(acc[3][1], xb.y, wd1); fma2(acc[3][2], xb.y, wd2); fma2(acc[3][3], xb.y, wd3);
    }
    float af[8][4];
    #pragma unroll
    for (int p = 0; p < 4; ++p)
        #pragma unroll
        for (int j = 0; j < 4; ++j) {
            float2 v = upk(acc[p][j]);
            af[2 * p][j] = v.x;
            af[2 * p + 1][j] = v.y;
        }
    float4 w2q = *(const float4*)&wn2[tx << 2];
    #pragma unroll
    for (int r = 0; r < 8; ++r) {
        float ss = 0.f;
        #pragma unroll
        for (int j = 0; j < 4; ++j) ss = fmaf(af[r][j], af[r][j], ss);
        #pragma unroll
        for (int off = 16; off >= 1; off >>= 1) ss += __shfl_xor_sync(0xffffffffu, ss, off);
        float sc = rsqrtf(ss * (1.f / DM) + 1e-5f);
        long t = t0 + ty * 8 + r;
        float4 uq = *(const float4*)&g_u[t * DM + (tx << 2)];
        float4 ov = make_float4(af[r][0] * sc * w2q.x + uq.x,
                                af[r][1] * sc * w2q.y + uq.y,
                                af[r][2] * sc * w2q.z + uq.z,
                                af[r][3] * sc * w2q.w + uq.w);
        *(float4*)&g_m[t * DM + (tx << 2)] = ov;
    }
}

// ---------------- K7: w = swish(W_wp@xn+b) ; out = W_op@(w*m)+b + x ---------------
__global__ void k_final(const float* __restrict__ Wwp, const float* __restrict__ bwp,
                        const float* __restrict__ Wop, const float* __restrict__ bop,
                        const float* __restrict__ x, float* __restrict__ out) {
    extern __shared__ float sm[];
    float* sxn  = sm;                      // [i][t] 64*68
    float* smm  = sxn + 64 * 68;           // [t][c] 64*132
    float* swpT = smm + 64 * 132;          // [i][c] 64*132
    float* sopT = swpT + 64 * 132;         // [c][o] 128*68
    int tid = threadIdx.x;
    long t0 = (long)blockIdx.x * 64;

    for (int idx = tid; idx < 64 * DM; idx += 256) {
        int c = idx & 127, t = idx >> 7;
        smm[t * 132 + c] = g_m[(t0 + t) * DM + c];
    }
    for (int idx = tid; idx < 64 * 64; idx += 256) {
        int i = idx & 63, t = idx >> 6;
        sxn[i * 68 + t] = g_xn[(t0 + t) * DMO + i];
    }
    for (int idx = tid; idx < DM * DMO; idx += 256) {
        int i = idx & 63, c = idx >> 6;
        swpT[i * 132 + c] = Wwp[c * DMO + i];
    }
    for (int idx = tid; idx < DMO * DM; idx += 256) {
        int c = idx & 127, o = idx >> 7;
        sopT[c * 68 + o] = Wop[o * DM + c];
    }
    __syncthreads();
    int tx = tid & 31, ty = tid >> 5;
    {
        ull acc[4][4] = {};
        for (int i = 0; i < DMO; ++i) {
            float4 w4 = *(const float4*)&swpT[i * 132 + (tx << 2)];
            ull wd0 = pk2(w4.x, w4.x), wd1 = pk2(w4.y, w4.y);
            ull wd2 = pk2(w4.z, w4.z), wd3 = pk2(w4.w, w4.w);
            ulonglong2 xa = *(const ulonglong2*)&sxn[i * 68 + ty * 8];
            ulonglong2 xb = *(const ulonglong2*)&sxn[i * 68 + ty * 8 + 4];
            fma2(acc[0][0], xa.x, wd0); fma2(acc[0][1], xa.x, wd1); fma2(acc[0][2], xa.x, wd2); fma2(acc[0][3], xa.x, wd3);
            fma2(acc[1][0], xa.y, wd0); fma2(acc[1][1], xa.y, wd1); fma2(acc[1][2], xa.y, wd2); fma2(acc[1][3], xa.y, wd3);
            fma2(acc[2][0], xb.x, wd0); fma2(acc[2][1], xb.x, wd1); fma2(acc[2][2], xb.x, wd2); fma2(acc[2][3], xb.x, wd3);
            fma2(acc[3][0], xb.y, wd0); fma2(acc[3][1], xb.y, wd1); fma2(acc[3][2], xb.y, wd2); fma2(acc[3][3], xb.y, wd3);
        }
        float4 bq = *(const float4*)&bwp[tx << 2];
        float bj[4] = {bq.x, bq.y, bq.z, bq.w};
        #pragma unroll
        for (int p = 0; p < 4; ++p)
            #pragma unroll
            for (int j = 0; j < 4; ++j) {
                float2 v = upk(acc[p][j]);
                int c = (tx << 2) + j;
                int ta = ty * 8 + 2 * p;
                float va = v.x + bj[j], vb = v.y + bj[j];
                float wa = va / (1.f + __expf(-va));
                float wb = vb / (1.f + __expf(-vb));
                smm[ta * 132 + c] *= wa;
                smm[(ta + 1) * 132 + c] *= wb;
            }
    }
    __syncthreads();
    {
        int rowg = tid >> 4;           // 16 groups x 4 rows
        int o4 = (tid & 15) << 2;
        float a2[4][4] = {};
        for (int c = 0; c < DM; c += 4) {
            float4 q0 = *(const float4*)&sopT[(c + 0) * 68 + o4];
            float4 q1 = *(const float4*)&sopT[(c + 1) * 68 + o4];
            float4 q2 = *(const float4*)&sopT[(c + 2) * 68 + o4];
            float4 q3 = *(const float4*)&sopT[(c + 3) * 68 + o4];
            #pragma unroll
            for (int rr = 0; rr < 4; ++rr) {
                float4 pv = *(const float4*)&smm[(rowg * 4 + rr) * 132 + c];
                a2[rr][0] = fmaf(pv.x, q0.x, fmaf(pv.y, q1.x, fmaf(pv.z, q2.x, fmaf(pv.w, q3.x, a2[rr][0]))));
                a2[rr][1] = fmaf(pv.x, q0.y, fmaf(pv.y, q1.y, fmaf(pv.z, q2.y, fmaf(pv.w, q3.y, a2[rr][1]))));
                a2[rr][2] = fmaf(pv.x, q0.z, fmaf(pv.y, q1.z, fmaf(pv.z, q2.z, fmaf(pv.w, q3.z, a2[rr][2]))));
                a2[rr][3] = fmaf(pv.x, q0.w, fmaf(pv.y, q1.w, fmaf(pv.z, q2.w, fmaf(pv.w, q3.w, a2[rr][3]))));
            }
        }
        float4 bq = *(const float4*)&bop[o4];
        #pragma unroll
        for (int rr = 0; rr < 4; ++rr) {
            long tg = t0 + rowg * 4 + rr;
            float4 xq = *(const float4*)&x[tg * DMO + o4];
            float4 ov = make_float4(a2[rr][0] + bq.x + xq.x, a2[rr][1] + bq.y + xq.y,
                                    a2[rr][2] + bq.z + xq.z, a2[rr][3] + bq.w + xq.w);
            *(float4*)&out[tg * DMO + o4] = ov;
        }
    }
}

// ---------------- launch -----------------------------------------------------------
extern "C" void kernel_launch(void* const* d_in, const int* in_sizes, int n_in,
                              void* d_out, int out_size) {
    const float* x    = (const float*)d_in[0];
    const float* wn1  = (const float*)d_in[1];
    const float* wn2  = (const float*)d_in[2];
    const float* Wip  = (const float*)d_in[3];
    const float* bip  = (const float*)d_in[4];
    const float* Wfp  = (const float*)d_in[5];
    const float* bfp  = (const float*)d_in[6];
    const float* Wwp  = (const float*)d_in[7];
    const float* bwp  = (const float*)d_in[8];
    const float* Wop  = (const float*)d_in[9];
    const float* bop  = (const float*)d_in[10];
    const float* Win  = (const float*)d_in[11];
    const float* cw   = (const float*)d_in[12];
    const float* cb   = (const float*)d_in[13];
    const float* Xp   = (const float*)d_in[14];
    const float* Wdt  = (const float*)d_in[15];
    const float* bdt  = (const float*)d_in[16];
    const float* Alog = (const float*)d_in[17];
    const float* Dpar = (const float*)d_in[18];
    const float* Wmo  = (const float*)d_in[19];
    float* out = (float*)d_out;

    const int SM_K1 = (64 * 68 + 64 * 132 + 64) * 4;
    const int SM_K2 = (128 * 68 + 128 * 132) * 4;
    const int SM_K4 = (16640 + 40 * 260 + 64 * 40) * 4;
    const int SM_K6 = (256 * 68 + 256 * 132) * 4;
    const int SM_K7 = (64 * 68 + 64 * 132 + 64 * 132 + 128 * 68) * 4;

    cudaFuncSetAttribute(k_rms_u,   cudaFuncAttributeMaxDynamicSharedMemorySize, SM_K1);
    cudaFuncSetAttribute(k_inproj,  cudaFuncAttributeMaxDynamicSharedMemorySize, SM_K2);
    cudaFuncSetAttribute(k_xproj,   cudaFuncAttributeMaxDynamicSharedMemorySize, SM_K4);
    cudaFuncSetAttribute(k_outproj, cudaFuncAttributeMaxDynamicSharedMemorySize, SM_K6);
    cudaFuncSetAttribute(k_final,   cudaFuncAttributeMaxDynamicSharedMemorySize, SM_K7);

    k_combine<<<32, 256>>>(Wfp, Wip, bip, bfp);
    k_rms_u<<<TOK / 64, 256, SM_K1>>>(x, wn1);
    k_inproj<<<dim3(TOK / 64, 4), 256, SM_K2>>>(Win);
    k_conv<<<NCH, 256>>>(cw, cb);
    k_xproj<<<TOK / 64, 256, SM_K4>>>(Xp, Wdt, bdt);
    k_scan1<<<NUNIT / 16, 256>>>(Alog);
    k_scan2<<<64, 256>>>();
    k_scan3<<<NUNIT / 16, 256>>>(Alog, Dpar);
    k_outproj<<<TOK / 64, 256, SM_K6>>>(Wmo, wn2);
    k_final<<<TOK / 64, 256, SM_K7>>>(Wwp, bwp, Wop, bop, x, out);
}